// round 3
// baseline (speedup 1.0000x reference)
#include <cuda_runtime.h>

#define SEQ    8192
#define NH     32
#define NKV    8
#define HD     128
#define QSIZE  (NH * HD)            // 4096
#define KVSIZE (NKV * HD)           // 1024
#define ROW    (QSIZE + 2 * KVSIZE) // 6144
#define EPSV   1e-6f

#define WARPS_PER_BLOCK 8
#define THREADS 256

// Rows of norm+rope work: SEQ * (NH + NKV) = 8192*40 = 327680 → /8 warps = 40960 blocks
#define QK_BLOCKS ((SEQ * (NH + NKV)) / WARPS_PER_BLOCK)
// V copy: SEQ*KVSIZE floats = 8388608 → /4 (float4) = 2097152 → /256 = 8192 blocks
#define V_FLOAT4  ((SEQ * KVSIZE) / 4)
#define V_BLOCKS  (V_FLOAT4 / THREADS)

__global__ __launch_bounds__(THREADS)
void qknorm_rope_kernel(const float* __restrict__ qkv,
                        const float* __restrict__ qw,
                        const float* __restrict__ kw,
                        const float* __restrict__ cosw,
                        const float* __restrict__ sinw,
                        float* __restrict__ out)
{
    if (blockIdx.x < QK_BLOCKS) {
        const int warp = threadIdx.x >> 5;
        const int lane = threadIdx.x & 31;
        const int row  = blockIdx.x * WARPS_PER_BLOCK + warp;  // 0 .. 327679
        const int s = row / (NH + NKV);
        const int h = row % (NH + NKV);

        const float* __restrict__ src;
        float*       __restrict__ dst;
        const float* __restrict__ w;
        if (h < NH) {
            src = qkv + (size_t)s * ROW + h * HD;
            dst = out + (size_t)s * QSIZE + h * HD;
            w   = qw;
        } else {
            const int kh = h - NH;
            src = qkv + (size_t)s * ROW + QSIZE + kh * HD;
            dst = out + (size_t)SEQ * QSIZE + (size_t)s * KVSIZE + kh * HD;
            w   = kw;
        }

        const int d0 = lane * 4;
        float4 x = *reinterpret_cast<const float4*>(src + d0);

        // sum of squares over the 128-wide head
        float ss = x.x * x.x + x.y * x.y + x.z * x.z + x.w * x.w;
        #pragma unroll
        for (int off = 16; off > 0; off >>= 1)
            ss += __shfl_xor_sync(0xffffffffu, ss, off);

        const float inv = rsqrtf(ss * (1.0f / HD) + EPSV);

        float4 wv = *reinterpret_cast<const float4*>(w    + d0);
        float4 cv = *reinterpret_cast<const float4*>(cosw + d0);
        float4 sv = *reinterpret_cast<const float4*>(sinw + d0);

        float n0 = x.x * inv * wv.x;
        float n1 = x.y * inv * wv.y;
        float n2 = x.z * inv * wv.z;
        float n3 = x.w * inv * wv.w;

        // rotate_half partner: element d+64 (lane<16) or d-64 (lane>=16)
        // = same float4 slot in lane ^ 16.
        float p0 = __shfl_xor_sync(0xffffffffu, n0, 16);
        float p1 = __shfl_xor_sync(0xffffffffu, n1, 16);
        float p2 = __shfl_xor_sync(0xffffffffu, n2, 16);
        float p3 = __shfl_xor_sync(0xffffffffu, n3, 16);

        const float sign = (lane < 16) ? -1.0f : 1.0f;

        float4 o;
        o.x = n0 * cv.x + sign * p0 * sv.x;
        o.y = n1 * cv.y + sign * p1 * sv.y;
        o.z = n2 * cv.z + sign * p2 * sv.z;
        o.w = n3 * cv.w + sign * p3 * sv.w;

        *reinterpret_cast<float4*>(dst + d0) = o;
    } else {
        // V passthrough: strided gather from qkv rows, contiguous write.
        const int idx = (blockIdx.x - QK_BLOCKS) * THREADS + threadIdx.x;  // < V_FLOAT4
        const int f4_per_row = KVSIZE / 4;  // 256
        const int s = idx / f4_per_row;
        const int c = idx % f4_per_row;
        const float4* src = reinterpret_cast<const float4*>(
            qkv + (size_t)s * ROW + QSIZE + KVSIZE) + c;
        float4* dst = reinterpret_cast<float4*>(
            out + (size_t)SEQ * (QSIZE + KVSIZE)) + idx;
        *dst = *src;
    }
}

extern "C" void kernel_launch(void* const* d_in, const int* in_sizes, int n_in,
                              void* d_out, int out_size)
{
    const float* qkv  = (const float*)d_in[0];
    const float* qw   = (const float*)d_in[1];
    const float* kw   = (const float*)d_in[2];
    const float* cosw = (const float*)d_in[3];
    const float* sinw = (const float*)d_in[4];
    float* out = (float*)d_out;

    qknorm_rope_kernel<<<QK_BLOCKS + V_BLOCKS, THREADS>>>(qkv, qw, kw, cosw, sinw, out);
}

// round 5
// speedup vs baseline: 1.0725x; 1.0725x over previous
#include <cuda_runtime.h>

#define SEQ    8192
#define NH     32
#define NKV    8
#define HD     128
#define QSIZE  (NH * HD)            // 4096
#define KVSIZE (NKV * HD)           // 1024
#define ROW    (QSIZE + 2 * KVSIZE) // 6144
#define EPSV   1e-6f

#define WARPS_PER_BLOCK 8
#define THREADS 256

// QK rows: SEQ*(NH+NKV)=327680. 2 rows per warp -> 163840 warp-tasks -> /8 = 20480 blocks
#define QK_TASKS  ((SEQ * (NH + NKV)) / 2)
#define QK_BLOCKS (QK_TASKS / WARPS_PER_BLOCK)
// V copy: SEQ*KVSIZE/4 float4 = 2097152; 2 per thread -> /512 = 4096 blocks
#define V_FLOAT4  ((SEQ * KVSIZE) / 4)
#define V_BLOCKS  (V_FLOAT4 / (THREADS * 2))

__device__ __forceinline__ void row_ptrs(int row, const float* qkv, float* out,
                                         const float* qw, const float* kw,
                                         const float*& src, float*& dst, const float*& w)
{
    const int s = row / (NH + NKV);
    const int h = row - s * (NH + NKV);
    if (h < NH) {
        src = qkv + (size_t)s * ROW + h * HD;
        dst = out + (size_t)s * QSIZE + h * HD;
        w   = qw;
    } else {
        const int kh = h - NH;
        src = qkv + (size_t)s * ROW + QSIZE + kh * HD;
        dst = out + (size_t)SEQ * QSIZE + (size_t)s * KVSIZE + kh * HD;
        w   = kw;
    }
}

__global__ __launch_bounds__(THREADS)
void qknorm_rope_kernel(const float* __restrict__ qkv,
                        const float* __restrict__ qw,
                        const float* __restrict__ kw,
                        const float* __restrict__ cosw,
                        const float* __restrict__ sinw,
                        float* __restrict__ out)
{
    if (blockIdx.x < QK_BLOCKS) {
        const int warp = threadIdx.x >> 5;
        const int lane = threadIdx.x & 31;
        const int task = blockIdx.x * WARPS_PER_BLOCK + warp;
        const int row0 = task * 2;
        const int row1 = row0 + 1;
        const int d0 = lane * 4;

        const float *srcA, *srcB, *wA, *wB;
        float *dstA, *dstB;
        row_ptrs(row0, qkv, out, qw, kw, srcA, dstA, wA);
        row_ptrs(row1, qkv, out, qw, kw, srcB, dstB, wB);

        // Two independent 16B loads up front (MLP=2), streaming (no reuse).
        float4 xa = __ldcs(reinterpret_cast<const float4*>(srcA + d0));
        float4 xb = __ldcs(reinterpret_cast<const float4*>(srcB + d0));

        float ssa = xa.x * xa.x + xa.y * xa.y + xa.z * xa.z + xa.w * xa.w;
        float ssb = xb.x * xb.x + xb.y * xb.y + xb.z * xb.z + xb.w * xb.w;

        // Interleaved butterfly reductions: chain B hides chain A's SHFL latency.
        #pragma unroll
        for (int off = 16; off > 0; off >>= 1) {
            ssa += __shfl_xor_sync(0xffffffffu, ssa, off);
            ssb += __shfl_xor_sync(0xffffffffu, ssb, off);
        }

        const float inva = rsqrtf(ssa * (1.0f / HD) + EPSV);
        const float invb = rsqrtf(ssb * (1.0f / HD) + EPSV);

        float4 wva = *reinterpret_cast<const float4*>(wA   + d0);
        float4 wvb = *reinterpret_cast<const float4*>(wB   + d0);
        float4 cv  = *reinterpret_cast<const float4*>(cosw + d0);
        float4 sv  = *reinterpret_cast<const float4*>(sinw + d0);

        float a0 = xa.x * inva * wva.x, a1 = xa.y * inva * wva.y;
        float a2 = xa.z * inva * wva.z, a3 = xa.w * inva * wva.w;
        float b0 = xb.x * invb * wvb.x, b1 = xb.y * invb * wvb.y;
        float b2 = xb.z * invb * wvb.z, b3 = xb.w * invb * wvb.w;

        // rotate_half partner lives at lane^16, same float4 slot. Interleave A/B.
        float pa0 = __shfl_xor_sync(0xffffffffu, a0, 16);
        float pb0 = __shfl_xor_sync(0xffffffffu, b0, 16);
        float pa1 = __shfl_xor_sync(0xffffffffu, a1, 16);
        float pb1 = __shfl_xor_sync(0xffffffffu, b1, 16);
        float pa2 = __shfl_xor_sync(0xffffffffu, a2, 16);
        float pb2 = __shfl_xor_sync(0xffffffffu, b2, 16);
        float pa3 = __shfl_xor_sync(0xffffffffu, a3, 16);
        float pb3 = __shfl_xor_sync(0xffffffffu, b3, 16);

        const float sign = (lane < 16) ? -1.0f : 1.0f;

        float4 oa, ob;
        oa.x = a0 * cv.x + sign * pa0 * sv.x;
        oa.y = a1 * cv.y + sign * pa1 * sv.y;
        oa.z = a2 * cv.z + sign * pa2 * sv.z;
        oa.w = a3 * cv.w + sign * pa3 * sv.w;
        ob.x = b0 * cv.x + sign * pb0 * sv.x;
        ob.y = b1 * cv.y + sign * pb1 * sv.y;
        ob.z = b2 * cv.z + sign * pb2 * sv.z;
        ob.w = b3 * cv.w + sign * pb3 * sv.w;

        __stcs(reinterpret_cast<float4*>(dstA + d0), oa);
        __stcs(reinterpret_cast<float4*>(dstB + d0), ob);
    } else {
        // V passthrough: 2 float4 per thread, streaming hints.
        const int vblock = blockIdx.x - QK_BLOCKS;
        const int i0 = vblock * (THREADS * 2) + threadIdx.x;
        const int i1 = i0 + THREADS;
        const float* vbase = qkv + QSIZE + KVSIZE;
        float* vout = out + (size_t)SEQ * (QSIZE + KVSIZE);

        // 256 float4 per row -> shift/mask
        const int s0 = i0 >> 8, c0 = i0 & 255;
        const int s1 = i1 >> 8, c1 = i1 & 255;

        float4 v0 = __ldcs(reinterpret_cast<const float4*>(vbase + (size_t)s0 * ROW) + c0);
        float4 v1 = __ldcs(reinterpret_cast<const float4*>(vbase + (size_t)s1 * ROW) + c1);
        __stcs(reinterpret_cast<float4*>(vout) + i0, v0);
        __stcs(reinterpret_cast<float4*>(vout) + i1, v1);
    }
}

extern "C" void kernel_launch(void* const* d_in, const int* in_sizes, int n_in,
                              void* d_out, int out_size)
{
    const float* qkv  = (const float*)d_in[0];
    const float* qw   = (const float*)d_in[1];
    const float* kw   = (const float*)d_in[2];
    const float* cosw = (const float*)d_in[3];
    const float* sinw = (const float*)d_in[4];
    float* out = (float*)d_out;

    qknorm_rope_kernel<<<QK_BLOCKS + V_BLOCKS, THREADS>>>(qkv, qw, kw, cosw, sinw, out);
}